// round 16
// baseline (speedup 1.0000x reference)
#include <cuda_runtime.h>
#include <cuda_fp16.h>
#include <math.h>
#include <stdint.h>

// Problem constants
#define BATCH   2
#define SEQ     2048
#define DM      2048
#define NH      16
#define KVH     4
#define HD      128
#define QKV_N   3072
#define BS      (BATCH*SEQ)   // 4096
#define QSCALE  0.08838834764831845f

// ---------------------------------------------------------------------------
// Scratch (pure fp16)
// ---------------------------------------------------------------------------
__device__ __half g_xn [BS * DM];
__device__ __half g_at [BS * DM];
__device__ __half g_wq [DM * QKV_N];
__device__ __half g_wo [DM * DM];

__device__ __half g_q [BATCH * NH  * SEQ * HD];
__device__ __half g_k [BATCH * KVH * SEQ * HD];
__device__ __half g_v [BATCH * KVH * SEQ * HD];

// ---------------------------------------------------------------------------
// PTX helpers
// ---------------------------------------------------------------------------
__device__ __forceinline__ uint32_t smem_u32(const void* p) {
    uint32_t a;
    asm("{ .reg .u64 t; cvta.to.shared.u64 t, %1; cvt.u32.u64 %0, t; }"
        : "=r"(a) : "l"(p));
    return a;
}
__device__ __forceinline__ void cp16(uint32_t dst, const void* src) {
    asm volatile("cp.async.cg.shared.global [%0], [%1], 16;"
                 :: "r"(dst), "l"(src));
}
__device__ __forceinline__ void cp_commit() {
    asm volatile("cp.async.commit_group;" ::: "memory");
}
template<int N>
__device__ __forceinline__ void cp_wait() {
    asm volatile("cp.async.wait_group %0;" :: "n"(N) : "memory");
}
__device__ __forceinline__ void ldsm_x4(uint32_t* r, uint32_t addr) {
    asm volatile("ldmatrix.sync.aligned.m8n8.x4.shared.b16 {%0,%1,%2,%3}, [%4];"
                 : "=r"(r[0]), "=r"(r[1]), "=r"(r[2]), "=r"(r[3]) : "r"(addr));
}
__device__ __forceinline__ void ldsm_x4t(uint32_t* r, uint32_t addr) {
    asm volatile("ldmatrix.sync.aligned.m8n8.x4.trans.shared.b16 {%0,%1,%2,%3}, [%4];"
                 : "=r"(r[0]), "=r"(r[1]), "=r"(r[2]), "=r"(r[3]) : "r"(addr));
}
__device__ __forceinline__ void mma_f16(float* d, const uint32_t* a, const uint32_t* b) {
    asm volatile(
        "mma.sync.aligned.m16n8k16.row.col.f32.f16.f16.f32 "
        "{%0,%1,%2,%3}, {%4,%5,%6,%7}, {%8,%9}, {%0,%1,%2,%3};"
        : "+f"(d[0]), "+f"(d[1]), "+f"(d[2]), "+f"(d[3])
        : "r"(a[0]), "r"(a[1]), "r"(a[2]), "r"(a[3]), "r"(b[0]), "r"(b[1]));
}
__device__ __forceinline__ void mma_f16_2(float* d, const uint32_t* a,
                                          uint32_t b0, uint32_t b1) {
    asm volatile(
        "mma.sync.aligned.m16n8k16.row.col.f32.f16.f16.f32 "
        "{%0,%1,%2,%3}, {%4,%5,%6,%7}, {%8,%9}, {%0,%1,%2,%3};"
        : "+f"(d[0]), "+f"(d[1]), "+f"(d[2]), "+f"(d[3])
        : "r"(a[0]), "r"(a[1]), "r"(a[2]), "r"(a[3]), "r"(b0), "r"(b1));
}

// ---------------------------------------------------------------------------
// RMSNorm (fp32 out)
// ---------------------------------------------------------------------------
__global__ void rmsnorm_kernel(const float* __restrict__ x,
                               const float* __restrict__ w,
                               float* __restrict__ y)
{
    __shared__ float red[256];
    int row = blockIdx.x;
    const float4* xr = (const float4*)(x + (size_t)row * DM);
    float s = 0.f;
    #pragma unroll
    for (int i = threadIdx.x; i < DM/4; i += 256) {
        float4 v = xr[i];
        s += v.x*v.x + v.y*v.y + v.z*v.z + v.w*v.w;
    }
    red[threadIdx.x] = s;
    __syncthreads();
    for (int st = 128; st > 0; st >>= 1) {
        if (threadIdx.x < st) red[threadIdx.x] += red[threadIdx.x + st];
        __syncthreads();
    }
    float rs = rsqrtf(red[0] * (1.0f/(float)DM) + 1e-5f);
    float4* yr = (float4*)(y + (size_t)row * DM);
    const float4* wr = (const float4*)w;
    #pragma unroll
    for (int i = threadIdx.x; i < DM/4; i += 256) {
        float4 v = xr[i];
        float4 ww = wr[i];
        v.x = v.x * rs * ww.x;
        v.y = v.y * rs * ww.y;
        v.z = v.z * rs * ww.z;
        v.w = v.w * rs * ww.w;
        yr[i] = v;
    }
}

// RMSNorm -> fp16
__global__ void rmsnorm_h_kernel(const float* __restrict__ x,
                                 const float* __restrict__ w,
                                 __half* __restrict__ yh)
{
    __shared__ float red[256];
    int row = blockIdx.x;
    const float4* xr = (const float4*)(x + (size_t)row * DM);
    float s = 0.f;
    #pragma unroll
    for (int i = threadIdx.x; i < DM/4; i += 256) {
        float4 v = xr[i];
        s += v.x*v.x + v.y*v.y + v.z*v.z + v.w*v.w;
    }
    red[threadIdx.x] = s;
    __syncthreads();
    for (int st = 128; st > 0; st >>= 1) {
        if (threadIdx.x < st) red[threadIdx.x] += red[threadIdx.x + st];
        __syncthreads();
    }
    float rs = rsqrtf(red[0] * (1.0f/(float)DM) + 1e-5f);
    const float4* wr = (const float4*)w;
    #pragma unroll
    for (int i = threadIdx.x; i < DM/4; i += 256) {
        float4 v = xr[i];
        float4 ww = wr[i];
        __half h[4];
        h[0] = __float2half(v.x*rs*ww.x);
        h[1] = __float2half(v.y*rs*ww.y);
        h[2] = __float2half(v.z*rs*ww.z);
        h[3] = __float2half(v.w*rs*ww.w);
        *(ulonglong1*)&yh[(size_t)row * DM + i*4] = *(ulonglong1*)h;
    }
}

// fp32 -> fp16 convert
__global__ void cvt_h_kernel(const float* __restrict__ x,
                             __half* __restrict__ xh, int n4)
{
    int i = blockIdx.x * blockDim.x + threadIdx.x;
    if (i >= n4) return;
    float4 v = ((const float4*)x)[i];
    __half h[4];
    h[0] = __float2half(v.x);
    h[1] = __float2half(v.y);
    h[2] = __float2half(v.z);
    h[3] = __float2half(v.w);
    *(ulonglong1*)&xh[(size_t)i*4] = *(ulonglong1*)h;
}

// ---------------------------------------------------------------------------
// GEMM tiling: CTA 128x128, 4 warps (128 thr), warp tile 64x64, k-chunk 64,
// 3-stage cp.async, one sync/chunk, 2 CTAs/SM.
// ---------------------------------------------------------------------------
#define A_STRIDE  144
#define B_STRIDE  272
#define AH_OFF    0
#define BH_OFF    18432      // 128*144
#define CHUNK_SZ  35840      // + 64*272
#define HG_SMEM   (3*CHUNK_SZ)   // 107520 -> 2 CTAs/SM
#define CT_STRIDE 136            // fp16 epilogue staging

// Per-chunk compute: warp 64x64 -> 8 ldsm feed 32 MMAs per kk.
#define GEMM_COMPUTE_CHUNK(base)                                              \
    do {                                                                      \
        _Pragma("unroll")                                                     \
        for (int kk = 0; kk < 4; kk++) {                                      \
            uint32_t aR[4][4];                                                \
            _Pragma("unroll")                                                 \
            for (int mt = 0; mt < 4; mt++) {                                  \
                int r = warpM*64 + mt*16 + (lane & 15);                       \
                uint32_t col = ((lane >> 4) * 16) + kk * 32;                  \
                ldsm_x4(aR[mt], (base) + AH_OFF + r*A_STRIDE + col);          \
            }                                                                 \
            uint32_t bR[4][4];                                                \
            _Pragma("unroll")                                                 \
            for (int nt = 0; nt < 4; nt++) {                                  \
                int r = kk*16 + (lane & 15);                                  \
                uint32_t col = (uint32_t)(warpN*64 + nt*16) * 2               \
                             + ((lane >> 4) * 16);                            \
                ldsm_x4t(bR[nt], (base) + BH_OFF + r*B_STRIDE + col);         \
            }                                                                 \
            _Pragma("unroll")                                                 \
            for (int mt = 0; mt < 4; mt++) {                                  \
                _Pragma("unroll")                                             \
                for (int n8 = 0; n8 < 8; n8++) {                              \
                    int nt = n8 >> 1, hf = (n8 & 1) * 2;                      \
                    mma_f16(acc[mt][n8], aR[mt], &bR[nt][hf]);                \
                }                                                             \
            }                                                                 \
        }                                                                     \
    } while (0)

// Loader: 128 threads; A 128 rows x 8 cp16, B 64 rows x 16 cp16.
#define GEMM_ISSUE_CHUNK(Aptr, Bptr, Ncols)                                   \
    auto issue = [&](int c) {                                                 \
        uint32_t base = sb + (uint32_t)(c % 3) * CHUNK_SZ;                    \
        int k0 = c * 64;                                                      \
        _Pragma("unroll")                                                     \
        for (int it = 0; it < 8; it++) {                                      \
            int idx = it * 128 + tid;                                         \
            int r  = idx >> 3;                                                \
            int kc = idx & 7;                                                 \
            cp16(base + AH_OFF + r * A_STRIDE + kc * 16,                      \
                 (Aptr) + (size_t)(rowBase + r) * K + k0 + kc*8);             \
        }                                                                     \
        _Pragma("unroll")                                                     \
        for (int it = 0; it < 8; it++) {                                      \
            int idx = it * 128 + tid;                                         \
            int r   = idx >> 4;                                               \
            int c16 = idx & 15;                                               \
            cp16(base + BH_OFF + r * B_STRIDE + c16 * 16,                     \
                 (Bptr) + (size_t)(k0 + r) * (Ncols) + colBase + c16*8);      \
        }                                                                     \
        cp_commit();                                                          \
    }

// out-proj GEMM: C = A@B + Resid (fp32 out)
__global__ void __launch_bounds__(128, 2)
hgemm_resid_kernel(const __half* __restrict__ Ah,
                   const __half* __restrict__ Bh,
                   const float* __restrict__ Resid, float* __restrict__ C,
                   int M, int N, int K)
{
    extern __shared__ char sm[];
    uint32_t sb = smem_u32(sm);

    int tid  = threadIdx.x;
    int lane = tid & 31;
    int warp = tid >> 5;
    int warpM = warp & 1;       // 64-row half
    int warpN = warp >> 1;      // 64-col half
    int rowBase = blockIdx.y * 128;
    int colBase = blockIdx.x * 128;

    float acc[4][8][4];
    #pragma unroll
    for (int i = 0; i < 4; i++)
        #pragma unroll
        for (int j = 0; j < 8; j++)
            #pragma unroll
            for (int q = 0; q < 4; q++) acc[i][j][q] = 0.f;

    int nC = K / 64;
    GEMM_ISSUE_CHUNK(Ah, Bh, N);

    issue(0);
    if (nC > 1) issue(1);

    for (int c = 0; c < nC; c++) {
        if (c + 1 < nC) { cp_wait<1>(); }
        else            { cp_wait<0>(); }
        __syncthreads();
        uint32_t base = sb + (uint32_t)(c % 3) * CHUNK_SZ;
        GEMM_COMPUTE_CHUNK(base);
        if (c + 2 < nC) issue(c + 2);
    }

    int rg = lane >> 2;
    int cg = (lane & 3) * 2;
    #pragma unroll
    for (int mt = 0; mt < 4; mt++) {
        #pragma unroll
        for (int n8 = 0; n8 < 8; n8++) {
            int r0 = rowBase + warpM*64 + mt*16 + rg;
            int cc = colBase + warpN*64 + n8*8 + cg;
            #pragma unroll
            for (int half = 0; half < 2; half++) {
                int r = r0 + half * 8;
                float2 v;
                v.x = acc[mt][n8][half*2+0];
                v.y = acc[mt][n8][half*2+1];
                float2 rv = *(const float2*)&Resid[(size_t)r * N + cc];
                v.x += rv.x; v.y += rv.y;
                *(float2*)&C[(size_t)r * N + cc] = v;
            }
        }
    }
}

// QKV GEMM with fused clip + RoPE + fp16 epilogue.
__global__ void __launch_bounds__(128, 2)
hgemm_qkv_kernel(const __half* __restrict__ Ah,
                 const __half* __restrict__ Bh,
                 const int* __restrict__ posids,
                 const float* __restrict__ rsin, const float* __restrict__ rcos,
                 __half* __restrict__ Qo,
                 __half* __restrict__ Ko,
                 __half* __restrict__ Vo)
{
    extern __shared__ char sm[];
    uint32_t sb = smem_u32(sm);

    const int N = QKV_N, K = DM;
    int tid  = threadIdx.x;
    int lane = tid & 31;
    int warp = tid >> 5;
    int warpM = warp & 1;
    int warpN = warp >> 1;
    int rowBase = blockIdx.y * 128;
    int colBase = blockIdx.x * 128;

    float acc[4][8][4];
    #pragma unroll
    for (int i = 0; i < 4; i++)
        #pragma unroll
        for (int j = 0; j < 8; j++)
            #pragma unroll
            for (int q = 0; q < 4; q++) acc[i][j][q] = 0.f;

    int nC = K / 64;
    GEMM_ISSUE_CHUNK(Ah, Bh, N);

    issue(0);
    if (nC > 1) issue(1);

    for (int c = 0; c < nC; c++) {
        if (c + 1 < nC) { cp_wait<1>(); }
        else            { cp_wait<0>(); }
        __syncthreads();
        uint32_t base = sb + (uint32_t)(c % 3) * CHUNK_SZ;
        GEMM_COMPUTE_CHUNK(base);
        if (c + 2 < nC) issue(c + 2);
    }
    __syncthreads();

    // Stage clipped tile in smem as fp16
    __half* Ct = (__half*)sm;
    int rg = lane >> 2;
    int cg = (lane & 3) * 2;
    #pragma unroll
    for (int mt = 0; mt < 4; mt++) {
        #pragma unroll
        for (int n8 = 0; n8 < 8; n8++) {
            int r0 = warpM*64 + mt*16 + rg;
            int cl = warpN*64 + n8*8 + cg;
            #pragma unroll
            for (int half = 0; half < 2; half++) {
                int r = r0 + half * 8;
                __half2 hv;
                hv.x = __float2half(fminf(8.f, fmaxf(-8.f, acc[mt][n8][half*2+0])));
                hv.y = __float2half(fminf(8.f, fmaxf(-8.f, acc[mt][n8][half*2+1])));
                *(__half2*)&Ct[r*CT_STRIDE + cl] = hv;
            }
        }
    }
    __syncthreads();

    // RoPE + scatter (fp16)
    int head = blockIdx.x;
    for (int idx = tid; idx < 128*128; idx += 128) {
        int r = idx >> 7;
        int d = idx & 127;
        int token = rowBase + r;
        int b = token >> 11;
        int s = token & 2047;
        float x = __half2float(Ct[r*CT_STRIDE + d]);
        if (head < NH + KVH) {
            int pos = posids[token];
            float cz = rcos[pos * HD + d];
            float sn = rsin[pos * HD + d];
            float other = (d < 64) ? -__half2float(Ct[r*CT_STRIDE + d + 64])
                                   :  __half2float(Ct[r*CT_STRIDE + d - 64]);
            float val = x * cz + other * sn;
            if (head < NH) {
                Qo[(((size_t)(b*NH + head)) * SEQ + s) * HD + d] =
                    __float2half(val * QSCALE);
            } else {
                Ko[(((size_t)(b*KVH + head - NH)) * SEQ + s) * HD + d] =
                    __float2half(val);
            }
        } else {
            Vo[(((size_t)(b*KVH + head - NH - KVH)) * SEQ + s) * HD + d] =
                __float2half(x);
        }
    }
}

// ---------------------------------------------------------------------------
// FlashAttention-2: BM=64, BN=64, 4 warps (128 thr), 2 CTAs/SM, fp16. (R14)
// ---------------------------------------------------------------------------
#define AT_STRIDE 272
#define AQ  0
#define AKV 17408
#define AKV_BUF 34816          // per buf: K 0 | V 17408
#define AMK (AKV + 2*AKV_BUF)  // 87040
#define ATT_SMEM (AMK + 512)   // 87552 -> 2 CTAs/SM

__global__ void __launch_bounds__(128, 2)
attn_fa2_kernel(const __half* __restrict__ Qh,
                const __half* __restrict__ Kh,
                const __half* __restrict__ Vh,
                const int* __restrict__ amask,
                __half* __restrict__ Oh)
{
    extern __shared__ char sm[];
    uint32_t sb = smem_u32(sm);
    int* mk = (int*)(sm + AMK);

    int tid  = threadIdx.x;
    int lane = tid & 31;
    int warp = tid >> 5;
    int qt = gridDim.x - 1 - blockIdx.x;
    int h  = blockIdx.y;
    int b  = blockIdx.z;
    int kvh = h >> 2;

    const __half* Qg  = Qh + ((size_t)(b*NH + h) * SEQ + qt*64) * HD;
    const __half* Kg  = Kh + ((size_t)(b*KVH + kvh) * SEQ) * HD;
    const __half* Vg  = Vh + ((size_t)(b*KVH + kvh) * SEQ) * HD;

    #pragma unroll
    for (int it = 0; it < 8; it++) {
        int idx = it * 128 + tid;
        int r = idx >> 4;
        int c = idx & 15;
        cp16(sb + AQ + r * AT_STRIDE + c*16, Qg + (size_t)r * HD + c*8);
    }
    cp_commit();

    auto issueKV = [&](int kt) {
        uint32_t base = sb + AKV + (kt & 1) * AKV_BUF;
        #pragma unroll
        for (int it = 0; it < 8; it++) {
            int idx = it * 128 + tid;
            int r = idx >> 4;
            int c = idx & 15;
            size_t go = (size_t)(kt*64 + r) * HD + c*8;
            uint32_t so = r * AT_STRIDE + c*16;
            cp16(base + 0     + so, Kg + go);
            cp16(base + 17408 + so, Vg + go);
        }
        cp_commit();
    };
    issueKV(0);

    float m0 = -1e30f, m1 = -1e30f, l0 = 0.f, l1 = 0.f;
    float o[16][4];
    #pragma unroll
    for (int i = 0; i < 16; i++)
        #pragma unroll
        for (int j = 0; j < 4; j++) o[i][j] = 0.f;

    int ktLast = qt;
    int rloc = (lane >> 2);

    for (int kt = 0; kt <= ktLast; kt++) {
        if (tid < 64)
            mk[(kt & 1)*64 + tid] = (amask[b*SEQ + kt*64 + tid] > 0) ? 0 : 1;
        cp_wait<0>();
        __syncthreads();
        if (kt < ktLast) issueKV(kt + 1);

        uint32_t kvbase = sb + AKV + (kt & 1) * AKV_BUF;
        const int* mkc = mk + (kt & 1)*64;

        float sacc[8][4];
        #pragma unroll
        for (int i = 0; i < 8; i++)
            #pragma unroll
            for (int j = 0; j < 4; j++) sacc[i][j] = 0.f;

        #pragma unroll
        for (int kk = 0; kk < 8; kk++) {
            uint32_t aQ[4];
            uint32_t aoff = (warp*16 + (lane & 15)) * AT_STRIDE
                          + kk*32 + ((lane >> 4) * 16);
            ldsm_x4(aQ, sb + AQ + aoff);
            uint32_t bK[4][4];
            #pragma unroll
            for (int nt = 0; nt < 4; nt++) {
                uint32_t boff = (uint32_t)(nt*16 + (lane & 15)) * AT_STRIDE
                              + kk*32 + ((lane >> 4) * 16);
                ldsm_x4(bK[nt], kvbase + boff);
            }
            #pragma unroll
            for (int n8 = 0; n8 < 8; n8++) {
                int nt = n8 >> 1;
                int lo = n8 & 1;
                mma_f16_2(sacc[n8], aQ, bK[nt][lo], bK[nt][lo+2]);
            }
        }

        bool needCausal = (kt == qt);
        int rg0 = qt*64 + warp*16 + rloc;
        #pragma unroll
        for (int n8 = 0; n8 < 8; n8++) {
            int c0 = n8*8 + (lane & 3)*2;
            float mb0 = mkc[c0]   ? -1e30f : 0.f;
            float mb1 = mkc[c0+1] ? -1e30f : 0.f;
            sacc[n8][0] += mb0; sacc[n8][1] += mb1;
            sacc[n8][2] += mb0; sacc[n8][3] += mb1;
            if (needCausal) {
                int cga = kt*64 + c0;
                if (cga     > rg0)     sacc[n8][0] = -1e30f;
                if (cga + 1 > rg0)     sacc[n8][1] = -1e30f;
                if (cga     > rg0 + 8) sacc[n8][2] = -1e30f;
                if (cga + 1 > rg0 + 8) sacc[n8][3] = -1e30f;
            }
        }
        float mx0 = m0, mx1 = m1;
        #pragma unroll
        for (int n8 = 0; n8 < 8; n8++) {
            mx0 = fmaxf(mx0, fmaxf(sacc[n8][0], sacc[n8][1]));
            mx1 = fmaxf(mx1, fmaxf(sacc[n8][2], sacc[n8][3]));
        }
        mx0 = fmaxf(mx0, __shfl_xor_sync(0xffffffff, mx0, 1));
        mx0 = fmaxf(mx0, __shfl_xor_sync(0xffffffff, mx0, 2));
        mx1 = fmaxf(mx1, __shfl_xor_sync(0xffffffff, mx1, 1));
        mx1 = fmaxf(mx1, __shfl_xor_sync(0xffffffff, mx1, 2));
        float ls0 = 0.f, ls1 = 0.f;
        #pragma unroll
        for (int n8 = 0; n8 < 8; n8++) {
            sacc[n8][0] = __expf(sacc[n8][0] - mx0);
            sacc[n8][1] = __expf(sacc[n8][1] - mx0);
            sacc[n8][2] = __expf(sacc[n8][2] - mx1);
            sacc[n8][3] = __expf(sacc[n8][3] - mx1);
            ls0 += sacc[n8][0] + sacc[n8][1];
            ls1 += sacc[n8][2] + sacc[n8][3];
        }
        ls0 += __shfl_xor_sync(0xffffffff, ls0, 1);
        ls0 += __shfl_xor_sync(0xffffffff, ls0, 2);
        ls1 += __shfl_xor_sync(0xffffffff, ls1, 1);
        ls1 += __shfl_xor_sync(0xffffffff, ls1, 2);
        float sc0 = __expf(m0 - mx0);
        float sc1 = __expf(m1 - mx1);
        m0 = mx0; m1 = mx1;
        l0 = l0 * sc0 + ls0;
        l1 = l1 * sc1 + ls1;

        uint32_t ph[8][2];
        #pragma unroll
        for (int n8 = 0; n8 < 8; n8++) {
            __half2 t;
            t.x = __float2half(sacc[n8][0]);
            t.y = __float2half(sacc[n8][1]);
            ph[n8][0] = *(uint32_t*)&t;
            t.x = __float2half(sacc[n8][2]);
            t.y = __float2half(sacc[n8][3]);
            ph[n8][1] = *(uint32_t*)&t;
        }

        #pragma unroll
        for (int n8 = 0; n8 < 16; n8++) {
            o[n8][0] *= sc0; o[n8][1] *= sc0;
            o[n8][2] *= sc1; o[n8][3] *= sc1;
        }

        #pragma unroll
        for (int ks = 0; ks < 4; ks++) {
            uint32_t aP[4] = {ph[2*ks][0], ph[2*ks][1], ph[2*ks+1][0], ph[2*ks+1][1]};
            uint32_t vV[8][4];
            #pragma unroll
            for (int nt = 0; nt < 8; nt++) {
                uint32_t voff = (uint32_t)(ks*16 + (lane & 15)) * AT_STRIDE
                              + (uint32_t)(nt*16)*2 + ((lane >> 4) * 16);
                ldsm_x4t(vV[nt], kvbase + 17408 + voff);
            }
            #pragma unroll
            for (int n8 = 0; n8 < 16; n8++) {
                int nt = n8 >> 1, hf = (n8 & 1) * 2;
                mma_f16(o[n8], aP, &vV[nt][hf]);
            }
        }
    }

    {
        float inv0 = 1.f / l0;
        float inv1 = 1.f / l1;
        #pragma unroll
        for (int half = 0; half < 2; half++) {
            int rg = qt*64 + warp*16 + rloc + half*8;
            float inv = half ? inv1 : inv0;
            size_t rowoff = (size_t)(b*SEQ + rg) * DM + (size_t)h * HD;
            #pragma unroll
            for (int n8 = 0; n8 < 16; n8++) {
                int c = n8*8 + (lane & 3)*2;
                __half2 pp;
                pp.x = __float2half(o[n8][half*2+0] * inv);
                pp.y = __float2half(o[n8][half*2+1] * inv);
                *(__half2*)&Oh[rowoff + c] = pp;
            }
        }
    }
}

// ---------------------------------------------------------------------------
// kernel_launch
// ---------------------------------------------------------------------------
extern "C" void kernel_launch(void* const* d_in, const int* in_sizes, int n_in,
                              void* d_out, int out_size)
{
    const float* hidden = (const float*)d_in[0];
    const int*   amask  = (const int*)  d_in[1];
    const int*   posids = (const int*)  d_in[2];
    const float* wqkv   = (const float*)d_in[3];
    const float* w_out  = (const float*)d_in[4];
    const float* n1w    = (const float*)d_in[5];
    const float* n2w    = (const float*)d_in[6];
    const float* rsin   = (const float*)d_in[7];
    const float* rcos   = (const float*)d_in[8];
    float* out = (float*)d_out;

    __half *p_xn, *p_at, *p_wq, *p_wo, *p_q, *p_k, *p_v;
    cudaGetSymbolAddress((void**)&p_xn,  g_xn);
    cudaGetSymbolAddress((void**)&p_at,  g_at);
    cudaGetSymbolAddress((void**)&p_wq,  g_wq);
    cudaGetSymbolAddress((void**)&p_wo,  g_wo);
    cudaGetSymbolAddress((void**)&p_q,   g_q);
    cudaGetSymbolAddress((void**)&p_k,   g_k);
    cudaGetSymbolAddress((void**)&p_v,   g_v);

    cudaFuncSetAttribute(hgemm_qkv_kernel,
                         cudaFuncAttributeMaxDynamicSharedMemorySize, HG_SMEM);
    cudaFuncSetAttribute(hgemm_resid_kernel,
                         cudaFuncAttributeMaxDynamicSharedMemorySize, HG_SMEM);
    cudaFuncSetAttribute(attn_fa2_kernel,
                         cudaFuncAttributeMaxDynamicSharedMemorySize, ATT_SMEM);

    // 1. pre-norm -> fp16
    rmsnorm_h_kernel<<<BS, 256>>>(hidden, n1w, p_xn);

    // weight conversions (fp16)
    cvt_h_kernel<<<(DM*QKV_N/4 + 255)/256, 256>>>(wqkv, p_wq, DM*QKV_N/4);
    cvt_h_kernel<<<(DM*DM/4 + 255)/256, 256>>>(w_out, p_wo, DM*DM/4);

    // 2. QKV projection + clip + RoPE (fused, fp16, 4-warp 64x64 warp tiles)
    {
        dim3 grid(QKV_N/128, BS/128);
        hgemm_qkv_kernel<<<grid, 128, HG_SMEM>>>(p_xn, p_wq,
                                                 posids, rsin, rcos,
                                                 p_q, p_k, p_v);
    }

    // 3. flash attention (FA2, fp16, BM=64, 2 CTAs/SM)
    {
        dim3 grid(SEQ/64, NH, BATCH);
        attn_fa2_kernel<<<grid, 128, ATT_SMEM>>>(p_q, p_k, p_v, amask, p_at);
    }

    // 4. out-proj + residual add (fp16, 4-warp 64x64 warp tiles)
    {
        dim3 grid(DM/128, BS/128);
        hgemm_resid_kernel<<<grid, 128, HG_SMEM>>>(p_at, p_wo,
                                                   hidden, out, BS, DM, DM);
    }

    // 5. post-norm
    rmsnorm_kernel<<<BS, 256>>>(out, n2w, out + (size_t)BS * DM);
}

// round 17
// speedup vs baseline: 1.1269x; 1.1269x over previous
#include <cuda_runtime.h>
#include <cuda_fp16.h>
#include <math.h>
#include <stdint.h>

// Problem constants
#define BATCH   2
#define SEQ     2048
#define DM      2048
#define NH      16
#define KVH     4
#define HD      128
#define QKV_N   3072
#define BS      (BATCH*SEQ)   // 4096
#define QSCALE  0.08838834764831845f

// ---------------------------------------------------------------------------
// Scratch (pure fp16)
// ---------------------------------------------------------------------------
__device__ __half g_xn [BS * DM];
__device__ __half g_at [BS * DM];
__device__ __half g_wq [DM * QKV_N];
__device__ __half g_wo [DM * DM];

__device__ __half g_q [BATCH * NH  * SEQ * HD];
__device__ __half g_k [BATCH * KVH * SEQ * HD];
__device__ __half g_v [BATCH * KVH * SEQ * HD];

// ---------------------------------------------------------------------------
// PTX helpers
// ---------------------------------------------------------------------------
__device__ __forceinline__ uint32_t smem_u32(const void* p) {
    uint32_t a;
    asm("{ .reg .u64 t; cvta.to.shared.u64 t, %1; cvt.u32.u64 %0, t; }"
        : "=r"(a) : "l"(p));
    return a;
}
__device__ __forceinline__ void cp16(uint32_t dst, const void* src) {
    asm volatile("cp.async.cg.shared.global [%0], [%1], 16;"
                 :: "r"(dst), "l"(src));
}
__device__ __forceinline__ void cp_commit() {
    asm volatile("cp.async.commit_group;" ::: "memory");
}
template<int N>
__device__ __forceinline__ void cp_wait() {
    asm volatile("cp.async.wait_group %0;" :: "n"(N) : "memory");
}
__device__ __forceinline__ void ldsm_x4(uint32_t* r, uint32_t addr) {
    asm volatile("ldmatrix.sync.aligned.m8n8.x4.shared.b16 {%0,%1,%2,%3}, [%4];"
                 : "=r"(r[0]), "=r"(r[1]), "=r"(r[2]), "=r"(r[3]) : "r"(addr));
}
__device__ __forceinline__ void ldsm_x4t(uint32_t* r, uint32_t addr) {
    asm volatile("ldmatrix.sync.aligned.m8n8.x4.trans.shared.b16 {%0,%1,%2,%3}, [%4];"
                 : "=r"(r[0]), "=r"(r[1]), "=r"(r[2]), "=r"(r[3]) : "r"(addr));
}
__device__ __forceinline__ void mma_f16(float* d, const uint32_t* a, const uint32_t* b) {
    asm volatile(
        "mma.sync.aligned.m16n8k16.row.col.f32.f16.f16.f32 "
        "{%0,%1,%2,%3}, {%4,%5,%6,%7}, {%8,%9}, {%0,%1,%2,%3};"
        : "+f"(d[0]), "+f"(d[1]), "+f"(d[2]), "+f"(d[3])
        : "r"(a[0]), "r"(a[1]), "r"(a[2]), "r"(a[3]), "r"(b[0]), "r"(b[1]));
}
__device__ __forceinline__ void mma_f16_2(float* d, const uint32_t* a,
                                          uint32_t b0, uint32_t b1) {
    asm volatile(
        "mma.sync.aligned.m16n8k16.row.col.f32.f16.f16.f32 "
        "{%0,%1,%2,%3}, {%4,%5,%6,%7}, {%8,%9}, {%0,%1,%2,%3};"
        : "+f"(d[0]), "+f"(d[1]), "+f"(d[2]), "+f"(d[3])
        : "r"(a[0]), "r"(a[1]), "r"(a[2]), "r"(a[3]), "r"(b0), "r"(b1));
}

// ---------------------------------------------------------------------------
// RMSNorm (fp32 out)
// ---------------------------------------------------------------------------
__global__ void rmsnorm_kernel(const float* __restrict__ x,
                               const float* __restrict__ w,
                               float* __restrict__ y)
{
    __shared__ float red[256];
    int row = blockIdx.x;
    const float4* xr = (const float4*)(x + (size_t)row * DM);
    float s = 0.f;
    #pragma unroll
    for (int i = threadIdx.x; i < DM/4; i += 256) {
        float4 v = xr[i];
        s += v.x*v.x + v.y*v.y + v.z*v.z + v.w*v.w;
    }
    red[threadIdx.x] = s;
    __syncthreads();
    for (int st = 128; st > 0; st >>= 1) {
        if (threadIdx.x < st) red[threadIdx.x] += red[threadIdx.x + st];
        __syncthreads();
    }
    float rs = rsqrtf(red[0] * (1.0f/(float)DM) + 1e-5f);
    float4* yr = (float4*)(y + (size_t)row * DM);
    const float4* wr = (const float4*)w;
    #pragma unroll
    for (int i = threadIdx.x; i < DM/4; i += 256) {
        float4 v = xr[i];
        float4 ww = wr[i];
        v.x = v.x * rs * ww.x;
        v.y = v.y * rs * ww.y;
        v.z = v.z * rs * ww.z;
        v.w = v.w * rs * ww.w;
        yr[i] = v;
    }
}

// RMSNorm -> fp16
__global__ void rmsnorm_h_kernel(const float* __restrict__ x,
                                 const float* __restrict__ w,
                                 __half* __restrict__ yh)
{
    __shared__ float red[256];
    int row = blockIdx.x;
    const float4* xr = (const float4*)(x + (size_t)row * DM);
    float s = 0.f;
    #pragma unroll
    for (int i = threadIdx.x; i < DM/4; i += 256) {
        float4 v = xr[i];
        s += v.x*v.x + v.y*v.y + v.z*v.z + v.w*v.w;
    }
    red[threadIdx.x] = s;
    __syncthreads();
    for (int st = 128; st > 0; st >>= 1) {
        if (threadIdx.x < st) red[threadIdx.x] += red[threadIdx.x + st];
        __syncthreads();
    }
    float rs = rsqrtf(red[0] * (1.0f/(float)DM) + 1e-5f);
    const float4* wr = (const float4*)w;
    #pragma unroll
    for (int i = threadIdx.x; i < DM/4; i += 256) {
        float4 v = xr[i];
        float4 ww = wr[i];
        __half h[4];
        h[0] = __float2half(v.x*rs*ww.x);
        h[1] = __float2half(v.y*rs*ww.y);
        h[2] = __float2half(v.z*rs*ww.z);
        h[3] = __float2half(v.w*rs*ww.w);
        *(ulonglong1*)&yh[(size_t)row * DM + i*4] = *(ulonglong1*)h;
    }
}

// fp32 -> fp16 convert, both weight matrices in ONE launch (grid-stride)
#define WQ_N4 (DM*QKV_N/4)
#define WO_N4 (DM*DM/4)
__global__ void cvt_weights_kernel(const float* __restrict__ wq,
                                   const float* __restrict__ wo,
                                   __half* __restrict__ wqh,
                                   __half* __restrict__ woh)
{
    int stride = gridDim.x * blockDim.x;
    for (int i = blockIdx.x * blockDim.x + threadIdx.x;
         i < WQ_N4 + WO_N4; i += stride) {
        const float* src;
        __half* dst;
        int j;
        if (i < WQ_N4) { src = wq; dst = wqh; j = i; }
        else           { src = wo; dst = woh; j = i - WQ_N4; }
        float4 v = ((const float4*)src)[j];
        __half h[4];
        h[0] = __float2half(v.x);
        h[1] = __float2half(v.y);
        h[2] = __float2half(v.z);
        h[3] = __float2half(v.w);
        *(ulonglong1*)&dst[(size_t)j*4] = *(ulonglong1*)h;
    }
}

// ---------------------------------------------------------------------------
// GEMM tiling (R11 config): CTA 128x128, 8 warps, k-chunk 64, 3-stage,
// one sync/chunk, 2 CTAs/SM.
// ---------------------------------------------------------------------------
#define A_STRIDE  144
#define B_STRIDE  272
#define AH_OFF    0
#define BH_OFF    18432      // 128*144
#define CHUNK_SZ  35840      // + 64*272
#define HG_SMEM   (3*CHUNK_SZ)   // 107520 -> 2 CTAs/SM
#define CT_STRIDE 136            // fp16 epilogue staging

#define GEMM_COMPUTE_CHUNK(base)                                              \
    do {                                                                      \
        _Pragma("unroll")                                                     \
        for (int kk = 0; kk < 4; kk++) {                                      \
            uint32_t aR[4][4];                                                \
            _Pragma("unroll")                                                 \
            for (int mt = 0; mt < 4; mt++) {                                  \
                int r = warpM*64 + mt*16 + (lane & 15);                       \
                uint32_t col = ((lane >> 4) * 16) + kk * 32;                  \
                ldsm_x4(aR[mt], (base) + AH_OFF + r*A_STRIDE + col);          \
            }                                                                 \
            uint32_t bR[2][4];                                                \
            _Pragma("unroll")                                                 \
            for (int nt = 0; nt < 2; nt++) {                                  \
                int r = kk*16 + (lane & 15);                                  \
                uint32_t col = (uint32_t)(warpN*32 + nt*16) * 2               \
                             + ((lane >> 4) * 16);                            \
                ldsm_x4t(bR[nt], (base) + BH_OFF + r*B_STRIDE + col);         \
            }                                                                 \
            _Pragma("unroll")                                                 \
            for (int mt = 0; mt < 4; mt++) {                                  \
                _Pragma("unroll")                                             \
                for (int n8 = 0; n8 < 4; n8++) {                              \
                    int nt = n8 >> 1, hf = (n8 & 1) * 2;                      \
                    mma_f16(acc[mt][n8], aR[mt], &bR[nt][hf]);                \
                }                                                             \
            }                                                                 \
        }                                                                     \
    } while (0)

#define GEMM_ISSUE_CHUNK(Aptr, Bptr, Ncols)                                   \
    auto issue = [&](int c) {                                                 \
        uint32_t base = sb + (uint32_t)(c % 3) * CHUNK_SZ;                    \
        int k0 = c * 64;                                                      \
        _Pragma("unroll")                                                     \
        for (int it = 0; it < 4; it++) {                                      \
            int idx = it * 256 + tid;                                         \
            int r  = idx >> 3;                                                \
            int kc = idx & 7;                                                 \
            cp16(base + AH_OFF + r * A_STRIDE + kc * 16,                      \
                 (Aptr) + (size_t)(rowBase + r) * K + k0 + kc*8);             \
        }                                                                     \
        _Pragma("unroll")                                                     \
        for (int it = 0; it < 4; it++) {                                      \
            int idx = it * 256 + tid;                                         \
            int r   = idx >> 4;                                               \
            int c16 = idx & 15;                                               \
            cp16(base + BH_OFF + r * B_STRIDE + c16 * 16,                     \
                 (Bptr) + (size_t)(k0 + r) * (Ncols) + colBase + c16*8);      \
        }                                                                     \
        cp_commit();                                                          \
    }

// out-proj GEMM: C = A@B + Resid (fp32 out)
__global__ void __launch_bounds__(256, 2)
hgemm_resid_kernel(const __half* __restrict__ Ah,
                   const __half* __restrict__ Bh,
                   const float* __restrict__ Resid, float* __restrict__ C,
                   int M, int N, int K)
{
    extern __shared__ char sm[];
    uint32_t sb = smem_u32(sm);

    int tid  = threadIdx.x;
    int lane = tid & 31;
    int warp = tid >> 5;
    int warpM = warp & 1;
    int warpN = warp >> 1;
    int rowBase = blockIdx.y * 128;
    int colBase = blockIdx.x * 128;

    float acc[4][4][4];
    #pragma unroll
    for (int i = 0; i < 4; i++)
        #pragma unroll
        for (int j = 0; j < 4; j++)
            #pragma unroll
            for (int q = 0; q < 4; q++) acc[i][j][q] = 0.f;

    int nC = K / 64;
    GEMM_ISSUE_CHUNK(Ah, Bh, N);

    issue(0);
    if (nC > 1) issue(1);

    for (int c = 0; c < nC; c++) {
        if (c + 1 < nC) { cp_wait<1>(); }
        else            { cp_wait<0>(); }
        __syncthreads();
        uint32_t base = sb + (uint32_t)(c % 3) * CHUNK_SZ;
        GEMM_COMPUTE_CHUNK(base);
        if (c + 2 < nC) issue(c + 2);
    }

    int rg = lane >> 2;
    int cg = (lane & 3) * 2;
    #pragma unroll
    for (int mt = 0; mt < 4; mt++) {
        #pragma unroll
        for (int n8 = 0; n8 < 4; n8++) {
            int r0 = rowBase + warpM*64 + mt*16 + rg;
            int cc = colBase + warpN*32 + n8*8 + cg;
            #pragma unroll
            for (int half = 0; half < 2; half++) {
                int r = r0 + half * 8;
                float2 v;
                v.x = acc[mt][n8][half*2+0];
                v.y = acc[mt][n8][half*2+1];
                float2 rv = *(const float2*)&Resid[(size_t)r * N + cc];
                v.x += rv.x; v.y += rv.y;
                *(float2*)&C[(size_t)r * N + cc] = v;
            }
        }
    }
}

// QKV GEMM with fused clip + RoPE + fp16 epilogue.
__global__ void __launch_bounds__(256, 2)
hgemm_qkv_kernel(const __half* __restrict__ Ah,
                 const __half* __restrict__ Bh,
                 const int* __restrict__ posids,
                 const float* __restrict__ rsin, const float* __restrict__ rcos,
                 __half* __restrict__ Qo,
                 __half* __restrict__ Ko,
                 __half* __restrict__ Vo)
{
    extern __shared__ char sm[];
    uint32_t sb = smem_u32(sm);

    const int N = QKV_N, K = DM;
    int tid  = threadIdx.x;
    int lane = tid & 31;
    int warp = tid >> 5;
    int warpM = warp & 1;
    int warpN = warp >> 1;
    int rowBase = blockIdx.y * 128;
    int colBase = blockIdx.x * 128;

    float acc[4][4][4];
    #pragma unroll
    for (int i = 0; i < 4; i++)
        #pragma unroll
        for (int j = 0; j < 4; j++)
            #pragma unroll
            for (int q = 0; q < 4; q++) acc[i][j][q] = 0.f;

    int nC = K / 64;
    GEMM_ISSUE_CHUNK(Ah, Bh, N);

    issue(0);
    if (nC > 1) issue(1);

    for (int c = 0; c < nC; c++) {
        if (c + 1 < nC) { cp_wait<1>(); }
        else            { cp_wait<0>(); }
        __syncthreads();
        uint32_t base = sb + (uint32_t)(c % 3) * CHUNK_SZ;
        GEMM_COMPUTE_CHUNK(base);
        if (c + 2 < nC) issue(c + 2);
    }
    __syncthreads();

    // Stage clipped tile in smem as fp16
    __half* Ct = (__half*)sm;
    int rg = lane >> 2;
    int cg = (lane & 3) * 2;
    #pragma unroll
    for (int mt = 0; mt < 4; mt++) {
        #pragma unroll
        for (int n8 = 0; n8 < 4; n8++) {
            int r0 = warpM*64 + mt*16 + rg;
            int cl = warpN*32 + n8*8 + cg;
            #pragma unroll
            for (int half = 0; half < 2; half++) {
                int r = r0 + half * 8;
                __half2 hv;
                hv.x = __float2half(fminf(8.f, fmaxf(-8.f, acc[mt][n8][half*2+0])));
                hv.y = __float2half(fminf(8.f, fmaxf(-8.f, acc[mt][n8][half*2+1])));
                *(__half2*)&Ct[r*CT_STRIDE + cl] = hv;
            }
        }
    }
    __syncthreads();

    // RoPE + scatter (fp16)
    int head = blockIdx.x;
    for (int idx = tid; idx < 128*128; idx += 256) {
        int r = idx >> 7;
        int d = idx & 127;
        int token = rowBase + r;
        int b = token >> 11;
        int s = token & 2047;
        float x = __half2float(Ct[r*CT_STRIDE + d]);
        if (head < NH + KVH) {
            int pos = posids[token];
            float cz = rcos[pos * HD + d];
            float sn = rsin[pos * HD + d];
            float other = (d < 64) ? -__half2float(Ct[r*CT_STRIDE + d + 64])
                                   :  __half2float(Ct[r*CT_STRIDE + d - 64]);
            float val = x * cz + other * sn;
            if (head < NH) {
                Qo[(((size_t)(b*NH + head)) * SEQ + s) * HD + d] =
                    __float2half(val * QSCALE);
            } else {
                Ko[(((size_t)(b*KVH + head - NH)) * SEQ + s) * HD + d] =
                    __float2half(val);
            }
        } else {
            Vo[(((size_t)(b*KVH + head - NH - KVH)) * SEQ + s) * HD + d] =
                __float2half(x);
        }
    }
}

// ---------------------------------------------------------------------------
// FlashAttention-2: BM=64, BN=64, 4 warps (128 thr), 2 CTAs/SM, fp16. (R14)
// ---------------------------------------------------------------------------
#define AT_STRIDE 272
#define AQ  0
#define AKV 17408
#define AKV_BUF 34816          // per buf: K 0 | V 17408
#define AMK (AKV + 2*AKV_BUF)  // 87040
#define ATT_SMEM (AMK + 512)   // 87552 -> 2 CTAs/SM

__global__ void __launch_bounds__(128, 2)
attn_fa2_kernel(const __half* __restrict__ Qh,
                const __half* __restrict__ Kh,
                const __half* __restrict__ Vh,
                const int* __restrict__ amask,
                __half* __restrict__ Oh)
{
    extern __shared__ char sm[];
    uint32_t sb = smem_u32(sm);
    int* mk = (int*)(sm + AMK);

    int tid  = threadIdx.x;
    int lane = tid & 31;
    int warp = tid >> 5;
    int qt = gridDim.x - 1 - blockIdx.x;
    int h  = blockIdx.y;
    int b  = blockIdx.z;
    int kvh = h >> 2;

    const __half* Qg  = Qh + ((size_t)(b*NH + h) * SEQ + qt*64) * HD;
    const __half* Kg  = Kh + ((size_t)(b*KVH + kvh) * SEQ) * HD;
    const __half* Vg  = Vh + ((size_t)(b*KVH + kvh) * SEQ) * HD;

    #pragma unroll
    for (int it = 0; it < 8; it++) {
        int idx = it * 128 + tid;
        int r = idx >> 4;
        int c = idx & 15;
        cp16(sb + AQ + r * AT_STRIDE + c*16, Qg + (size_t)r * HD + c*8);
    }
    cp_commit();

    auto issueKV = [&](int kt) {
        uint32_t base = sb + AKV + (kt & 1) * AKV_BUF;
        #pragma unroll
        for (int it = 0; it < 8; it++) {
            int idx = it * 128 + tid;
            int r = idx >> 4;
            int c = idx & 15;
            size_t go = (size_t)(kt*64 + r) * HD + c*8;
            uint32_t so = r * AT_STRIDE + c*16;
            cp16(base + 0     + so, Kg + go);
            cp16(base + 17408 + so, Vg + go);
        }
        cp_commit();
    };
    issueKV(0);

    float m0 = -1e30f, m1 = -1e30f, l0 = 0.f, l1 = 0.f;
    float o[16][4];
    #pragma unroll
    for (int i = 0; i < 16; i++)
        #pragma unroll
        for (int j = 0; j < 4; j++) o[i][j] = 0.f;

    int ktLast = qt;
    int rloc = (lane >> 2);

    for (int kt = 0; kt <= ktLast; kt++) {
        if (tid < 64)
            mk[(kt & 1)*64 + tid] = (amask[b*SEQ + kt*64 + tid] > 0) ? 0 : 1;
        cp_wait<0>();
        __syncthreads();
        if (kt < ktLast) issueKV(kt + 1);

        uint32_t kvbase = sb + AKV + (kt & 1) * AKV_BUF;
        const int* mkc = mk + (kt & 1)*64;

        float sacc[8][4];
        #pragma unroll
        for (int i = 0; i < 8; i++)
            #pragma unroll
            for (int j = 0; j < 4; j++) sacc[i][j] = 0.f;

        #pragma unroll
        for (int kk = 0; kk < 8; kk++) {
            uint32_t aQ[4];
            uint32_t aoff = (warp*16 + (lane & 15)) * AT_STRIDE
                          + kk*32 + ((lane >> 4) * 16);
            ldsm_x4(aQ, sb + AQ + aoff);
            uint32_t bK[4][4];
            #pragma unroll
            for (int nt = 0; nt < 4; nt++) {
                uint32_t boff = (uint32_t)(nt*16 + (lane & 15)) * AT_STRIDE
                              + kk*32 + ((lane >> 4) * 16);
                ldsm_x4(bK[nt], kvbase + boff);
            }
            #pragma unroll
            for (int n8 = 0; n8 < 8; n8++) {
                int nt = n8 >> 1;
                int lo = n8 & 1;
                mma_f16_2(sacc[n8], aQ, bK[nt][lo], bK[nt][lo+2]);
            }
        }

        bool needCausal = (kt == qt);
        int rg0 = qt*64 + warp*16 + rloc;
        #pragma unroll
        for (int n8 = 0; n8 < 8; n8++) {
            int c0 = n8*8 + (lane & 3)*2;
            float mb0 = mkc[c0]   ? -1e30f : 0.f;
            float mb1 = mkc[c0+1] ? -1e30f : 0.f;
            sacc[n8][0] += mb0; sacc[n8][1] += mb1;
            sacc[n8][2] += mb0; sacc[n8][3] += mb1;
            if (needCausal) {
                int cga = kt*64 + c0;
                if (cga     > rg0)     sacc[n8][0] = -1e30f;
                if (cga + 1 > rg0)     sacc[n8][1] = -1e30f;
                if (cga     > rg0 + 8) sacc[n8][2] = -1e30f;
                if (cga + 1 > rg0 + 8) sacc[n8][3] = -1e30f;
            }
        }
        float mx0 = m0, mx1 = m1;
        #pragma unroll
        for (int n8 = 0; n8 < 8; n8++) {
            mx0 = fmaxf(mx0, fmaxf(sacc[n8][0], sacc[n8][1]));
            mx1 = fmaxf(mx1, fmaxf(sacc[n8][2], sacc[n8][3]));
        }
        mx0 = fmaxf(mx0, __shfl_xor_sync(0xffffffff, mx0, 1));
        mx0 = fmaxf(mx0, __shfl_xor_sync(0xffffffff, mx0, 2));
        mx1 = fmaxf(mx1, __shfl_xor_sync(0xffffffff, mx1, 1));
        mx1 = fmaxf(mx1, __shfl_xor_sync(0xffffffff, mx1, 2));
        float ls0 = 0.f, ls1 = 0.f;
        #pragma unroll
        for (int n8 = 0; n8 < 8; n8++) {
            sacc[n8][0] = __expf(sacc[n8][0] - mx0);
            sacc[n8][1] = __expf(sacc[n8][1] - mx0);
            sacc[n8][2] = __expf(sacc[n8][2] - mx1);
            sacc[n8][3] = __expf(sacc[n8][3] - mx1);
            ls0 += sacc[n8][0] + sacc[n8][1];
            ls1 += sacc[n8][2] + sacc[n8][3];
        }
        ls0 += __shfl_xor_sync(0xffffffff, ls0, 1);
        ls0 += __shfl_xor_sync(0xffffffff, ls0, 2);
        ls1 += __shfl_xor_sync(0xffffffff, ls1, 1);
        ls1 += __shfl_xor_sync(0xffffffff, ls1, 2);
        float sc0 = __expf(m0 - mx0);
        float sc1 = __expf(m1 - mx1);
        m0 = mx0; m1 = mx1;
        l0 = l0 * sc0 + ls0;
        l1 = l1 * sc1 + ls1;

        uint32_t ph[8][2];
        #pragma unroll
        for (int n8 = 0; n8 < 8; n8++) {
            __half2 t;
            t.x = __float2half(sacc[n8][0]);
            t.y = __float2half(sacc[n8][1]);
            ph[n8][0] = *(uint32_t*)&t;
            t.x = __float2half(sacc[n8][2]);
            t.y = __float2half(sacc[n8][3]);
            ph[n8][1] = *(uint32_t*)&t;
        }

        #pragma unroll
        for (int n8 = 0; n8 < 16; n8++) {
            o[n8][0] *= sc0; o[n8][1] *= sc0;
            o[n8][2] *= sc1; o[n8][3] *= sc1;
        }

        #pragma unroll
        for (int ks = 0; ks < 4; ks++) {
            uint32_t aP[4] = {ph[2*ks][0], ph[2*ks][1], ph[2*ks+1][0], ph[2*ks+1][1]};
            uint32_t vV[8][4];
            #pragma unroll
            for (int nt = 0; nt < 8; nt++) {
                uint32_t voff = (uint32_t)(ks*16 + (lane & 15)) * AT_STRIDE
                              + (uint32_t)(nt*16)*2 + ((lane >> 4) * 16);
                ldsm_x4t(vV[nt], kvbase + 17408 + voff);
            }
            #pragma unroll
            for (int n8 = 0; n8 < 16; n8++) {
                int nt = n8 >> 1, hf = (n8 & 1) * 2;
                mma_f16(o[n8], aP, &vV[nt][hf]);
            }
        }
    }

    {
        float inv0 = 1.f / l0;
        float inv1 = 1.f / l1;
        #pragma unroll
        for (int half = 0; half < 2; half++) {
            int rg = qt*64 + warp*16 + rloc + half*8;
            float inv = half ? inv1 : inv0;
            size_t rowoff = (size_t)(b*SEQ + rg) * DM + (size_t)h * HD;
            #pragma unroll
            for (int n8 = 0; n8 < 16; n8++) {
                int c = n8*8 + (lane & 3)*2;
                __half2 pp;
                pp.x = __float2half(o[n8][half*2+0] * inv);
                pp.y = __float2half(o[n8][half*2+1] * inv);
                *(__half2*)&Oh[rowoff + c] = pp;
            }
        }
    }
}

// ---------------------------------------------------------------------------
// kernel_launch
// ---------------------------------------------------------------------------
extern "C" void kernel_launch(void* const* d_in, const int* in_sizes, int n_in,
                              void* d_out, int out_size)
{
    const float* hidden = (const float*)d_in[0];
    const int*   amask  = (const int*)  d_in[1];
    const int*   posids = (const int*)  d_in[2];
    const float* wqkv   = (const float*)d_in[3];
    const float* w_out  = (const float*)d_in[4];
    const float* n1w    = (const float*)d_in[5];
    const float* n2w    = (const float*)d_in[6];
    const float* rsin   = (const float*)d_in[7];
    const float* rcos   = (const float*)d_in[8];
    float* out = (float*)d_out;

    __half *p_xn, *p_at, *p_wq, *p_wo, *p_q, *p_k, *p_v;
    cudaGetSymbolAddress((void**)&p_xn,  g_xn);
    cudaGetSymbolAddress((void**)&p_at,  g_at);
    cudaGetSymbolAddress((void**)&p_wq,  g_wq);
    cudaGetSymbolAddress((void**)&p_wo,  g_wo);
    cudaGetSymbolAddress((void**)&p_q,   g_q);
    cudaGetSymbolAddress((void**)&p_k,   g_k);
    cudaGetSymbolAddress((void**)&p_v,   g_v);

    cudaFuncSetAttribute(hgemm_qkv_kernel,
                         cudaFuncAttributeMaxDynamicSharedMemorySize, HG_SMEM);
    cudaFuncSetAttribute(hgemm_resid_kernel,
                         cudaFuncAttributeMaxDynamicSharedMemorySize, HG_SMEM);
    cudaFuncSetAttribute(attn_fa2_kernel,
                         cudaFuncAttributeMaxDynamicSharedMemorySize, ATT_SMEM);

    // 1. weight conversions (single fused launch) + pre-norm -> fp16
    cvt_weights_kernel<<<1184, 512>>>(wqkv, w_out, p_wq, p_wo);
    rmsnorm_h_kernel<<<BS, 256>>>(hidden, n1w, p_xn);

    // 2. QKV projection + clip + RoPE (fused, fp16)
    {
        dim3 grid(QKV_N/128, BS/128);
        hgemm_qkv_kernel<<<grid, 256, HG_SMEM>>>(p_xn, p_wq,
                                                 posids, rsin, rcos,
                                                 p_q, p_k, p_v);
    }

    // 3. flash attention (FA2, fp16, BM=64, 2 CTAs/SM)
    {
        dim3 grid(SEQ/64, NH, BATCH);
        attn_fa2_kernel<<<grid, 128, ATT_SMEM>>>(p_q, p_k, p_v, amask, p_at);
    }

    // 4. out-proj + residual add (fp16)
    {
        dim3 grid(DM/128, BS/128);
        hgemm_resid_kernel<<<grid, 256, HG_SMEM>>>(p_at, p_wo,
                                                   hidden, out, BS, DM, DM);
    }

    // 5. post-norm
    rmsnorm_kernel<<<BS, 256>>>(out, n2w, out + (size_t)BS * DM);
}